// round 3
// baseline (speedup 1.0000x reference)
#include <cuda_runtime.h>
#include <math.h>

// Problem constants (fixed by dataset)
#define NROWS   22528      // B*P = 1024*22
#define HD      512        // hidden
#define G4      2048       // 4*H
#define TSTEPS  100
#define INW     324        // input width to layer0
#define KPAD    336        // padded static width (multiple of 16)
#define PPLAYERS 22

// ---------------- scratch (device globals; no runtime allocation) ----------------
__device__ float g_sbias[(size_t)NROWS * G4];   // static part of layer0 gates
__device__ float g_gates[(size_t)NROWS * G4];   // per-step gate buffer (reused layer0/1)
__device__ float g_xs[(size_t)NROWS * KPAD];    // padded static input rows
__device__ float g_wpad[(size_t)G4 * KPAD];     // padded W_ih0
__device__ float g_h0[(size_t)NROWS * HD];
__device__ float g_c0[(size_t)NROWS * HD];
__device__ float g_h1[(size_t)NROWS * HD];
__device__ float g_c1[(size_t)NROWS * HD];
__device__ float g_hid[(size_t)NROWS * 256];    // MLP hidden
__device__ float g_pos[(size_t)NROWS * 2];      // current position (autoregressive)

__device__ __forceinline__ float sigm(float x) { return 1.f / (1.f + __expf(-x)); }

// ---------------- generic fused tiled GEMM ----------------
// C[n][j] = sum_k A[n][k] * W[j][k]  (+ optional second A2/W2 pass)
//           (+ bias vec) (+ sbias matrix) (+ rank-2 pos term) (opt relu)
// Tile: 64 rows x 64 cols, 256 threads, 4x4 per thread, BK=16.
template<bool TWO, bool SB, bool BV, bool POS, bool RELUF>
__global__ __launch_bounds__(256) void gemm_fused(
    float* __restrict__ C, int ldc,
    const float* __restrict__ A1, int lda1, const float* __restrict__ W1, int ldw1, int K1,
    const float* __restrict__ A2, int lda2, const float* __restrict__ W2, int ldw2, int K2,
    const float* __restrict__ bvec,
    const float* __restrict__ sbp, int ldsb,
    const float* __restrict__ pos, const float* __restrict__ wpos, int ldwpos)
{
    __shared__ float As[16][68];
    __shared__ float Ws[16][68];
    const int m0 = blockIdx.x * 64;
    const int j0 = blockIdx.y * 64;
    const int t  = threadIdx.x;
    const int lrow = t >> 2;            // 0..63
    const int c4   = (t & 3) * 4;       // 0,4,8,12
    const int tx   = (t & 15) * 4;      // col offset 0..60
    const int ty   = (t >> 4) * 4;      // row offset 0..60

    float acc[4][4];
#pragma unroll
    for (int i = 0; i < 4; ++i)
#pragma unroll
        for (int j = 0; j < 4; ++j) acc[i][j] = 0.f;

    const int npass = TWO ? 2 : 1;
    for (int pass = 0; pass < npass; ++pass) {
        const float* A = (pass == 0) ? A1 : A2;
        const float* W = (pass == 0) ? W1 : W2;
        const int lda  = (pass == 0) ? lda1 : lda2;
        const int ldw  = (pass == 0) ? ldw1 : ldw2;
        const int K    = (pass == 0) ? K1 : K2;
        for (int k0 = 0; k0 < K; k0 += 16) {
            __syncthreads();
            float4 av = *(const float4*)(A + (size_t)(m0 + lrow) * lda + k0 + c4);
            float4 wv = *(const float4*)(W + (size_t)(j0 + lrow) * ldw + k0 + c4);
            As[c4 + 0][lrow] = av.x; As[c4 + 1][lrow] = av.y;
            As[c4 + 2][lrow] = av.z; As[c4 + 3][lrow] = av.w;
            Ws[c4 + 0][lrow] = wv.x; Ws[c4 + 1][lrow] = wv.y;
            Ws[c4 + 2][lrow] = wv.z; Ws[c4 + 3][lrow] = wv.w;
            __syncthreads();
#pragma unroll
            for (int k = 0; k < 16; ++k) {
                float4 a = *(const float4*)&As[k][ty];
                float4 b = *(const float4*)&Ws[k][tx];
                acc[0][0] += a.x * b.x; acc[0][1] += a.x * b.y;
                acc[0][2] += a.x * b.z; acc[0][3] += a.x * b.w;
                acc[1][0] += a.y * b.x; acc[1][1] += a.y * b.y;
                acc[1][2] += a.y * b.z; acc[1][3] += a.y * b.w;
                acc[2][0] += a.z * b.x; acc[2][1] += a.z * b.y;
                acc[2][2] += a.z * b.z; acc[2][3] += a.z * b.w;
                acc[3][0] += a.w * b.x; acc[3][1] += a.w * b.y;
                acc[3][2] += a.w * b.z; acc[3][3] += a.w * b.w;
            }
        }
    }

#pragma unroll
    for (int r = 0; r < 4; ++r) {
        const int n = m0 + ty + r;
        float p0 = 0.f, p1 = 0.f;
        if (POS) { p0 = pos[n * 2]; p1 = pos[n * 2 + 1]; }
#pragma unroll
        for (int cc = 0; cc < 4; ++cc) {
            const int j = j0 + tx + cc;
            float v = acc[r][cc];
            if (BV) v += bvec[j];
            if (SB) v += sbp[(size_t)n * ldsb + j];
            if (POS) v += p0 * wpos[(size_t)j * ldwpos] + p1 * wpos[(size_t)j * ldwpos + 1];
            if (RELUF) v = fmaxf(v, 0.f);
            C[(size_t)n * ldc + j] = v;
        }
    }
}

// ---------------- LSTM elementwise cell ----------------
__global__ void lstm_cell(const float* __restrict__ gates,
                          float* __restrict__ h, float* __restrict__ c)
{
    int idx = blockIdx.x * blockDim.x + threadIdx.x;   // over NROWS * (HD/4)
    if (idx >= NROWS * (HD / 4)) return;
    int n  = idx / (HD / 4);
    int u4 = (idx - n * (HD / 4)) * 4;
    const float* gr = gates + (size_t)n * G4;
    float4 gi = *(const float4*)(gr + u4);
    float4 gf = *(const float4*)(gr + HD + u4);
    float4 gg = *(const float4*)(gr + 2 * HD + u4);
    float4 go = *(const float4*)(gr + 3 * HD + u4);
    float4 cv = *(float4*)(c + (size_t)idx * 4);
    float4 hn, cn;
    cn.x = sigm(gf.x) * cv.x + sigm(gi.x) * tanhf(gg.x); hn.x = sigm(go.x) * tanhf(cn.x);
    cn.y = sigm(gf.y) * cv.y + sigm(gi.y) * tanhf(gg.y); hn.y = sigm(go.y) * tanhf(cn.y);
    cn.z = sigm(gf.z) * cv.z + sigm(gi.z) * tanhf(gg.z); hn.z = sigm(go.z) * tanhf(cn.z);
    cn.w = sigm(gf.w) * cv.w + sigm(gi.w) * tanhf(gg.w); hn.w = sigm(go.w) * tanhf(cn.w);
    *(float4*)(c + (size_t)idx * 4) = cn;
    *(float4*)(h + (size_t)idx * 4) = hn;
}

// ---------------- final linear (H/2 -> 2) + output write + pos update ----------------
__global__ void mlp_out(const float* __restrict__ hid, const float* __restrict__ Wfc2,
                        const float* __restrict__ bfc2, float* __restrict__ pos,
                        float* __restrict__ out, int t)
{
    int gt = blockIdx.x * blockDim.x + threadIdx.x;
    int warp = gt >> 5;
    int lane = gt & 31;
    if (warp >= NROWS) return;
    const float* hr = hid + (size_t)warp * 256;
    float a0 = 0.f, a1 = 0.f;
#pragma unroll
    for (int i = 0; i < 8; ++i) {
        int k = lane + i * 32;
        float hv = hr[k];
        a0 += hv * Wfc2[k];
        a1 += hv * Wfc2[256 + k];
    }
#pragma unroll
    for (int off = 16; off; off >>= 1) {
        a0 += __shfl_down_sync(0xFFFFFFFFu, a0, off);
        a1 += __shfl_down_sync(0xFFFFFFFFu, a1, off);
    }
    if (lane == 0) {
        a0 += bfc2[0]; a1 += bfc2[1];
        pos[warp * 2]     = a0;
        pos[warp * 2 + 1] = a1;
        size_t o = ((size_t)warp * TSTEPS + t) * 2;
        out[o]     = a0;
        out[o + 1] = a1;
    }
}

// ---------------- precompute kernels ----------------
__global__ void build_xs(const float* __restrict__ ctx, const float* __restrict__ ball,
                         const int* __restrict__ roles, const float* __restrict__ rtab,
                         float* __restrict__ xs)
{
    int idx = blockIdx.x * blockDim.x + threadIdx.x;
    if (idx >= NROWS * KPAD) return;
    int n = idx / KPAD;
    int col = idx - n * KPAD;
    float v = 0.f;
    if (col >= 2 && col < 4)         v = ball[(n / PPLAYERS) * 2 + (col - 2)];
    else if (col >= 4 && col < 260)  v = ctx[(size_t)n * 256 + (col - 4)];
    else if (col >= 260 && col < 324) v = rtab[roles[n] * 64 + (col - 260)];
    xs[idx] = v;
}

__global__ void pad_w(const float* __restrict__ W, float* __restrict__ Wp)
{
    int idx = blockIdx.x * blockDim.x + threadIdx.x;
    if (idx >= G4 * KPAD) return;
    int j = idx / KPAD;
    int col = idx - j * KPAD;
    Wp[idx] = (col < INW) ? W[(size_t)j * INW + col] : 0.f;
}

__global__ void init_state(const float* __restrict__ pos0, const float* __restrict__ Winit,
                           const float* __restrict__ binit,
                           float* __restrict__ h0, float* __restrict__ c0,
                           float* __restrict__ h1, float* __restrict__ c1)
{
    int idx = blockIdx.x * blockDim.x + threadIdx.x;
    if (idx >= NROWS * HD) return;
    int n = idx / HD;
    int u = idx - n * HD;
    h0[idx] = pos0[n * 2] * Winit[u * 2] + pos0[n * 2 + 1] * Winit[u * 2 + 1] + binit[u];
    c0[idx] = 0.f; h1[idx] = 0.f; c1[idx] = 0.f;
}

__global__ void init_pos(const float* __restrict__ pos0, float* __restrict__ pos)
{
    int idx = blockIdx.x * blockDim.x + threadIdx.x;
    if (idx < NROWS * 2) pos[idx] = pos0[idx];
}

// ---------------- launch ----------------
extern "C" void kernel_launch(void* const* d_in, const int* in_sizes, int n_in,
                              void* d_out, int out_size)
{
    (void)in_sizes; (void)out_size;
    // Handle presence/absence of the max_steps scalar in the input list.
    int base = (n_in == 18) ? 5 : 4;
    const float* context  = (const float*)d_in[0];
    const float* init_pos0= (const float*)d_in[1];
    const float* ball     = (const float*)d_in[2];
    const int*   roles    = (const int*)d_in[3];
    const float* role_tab = (const float*)d_in[base + 0];
    const float* W_ih0    = (const float*)d_in[base + 1];
    const float* W_hh0    = (const float*)d_in[base + 2];
    const float* b0       = (const float*)d_in[base + 3];
    const float* W_ih1    = (const float*)d_in[base + 4];
    const float* W_hh1    = (const float*)d_in[base + 5];
    const float* b1       = (const float*)d_in[base + 6];
    const float* W_fc1    = (const float*)d_in[base + 7];
    const float* b_fc1    = (const float*)d_in[base + 8];
    const float* W_fc2    = (const float*)d_in[base + 9];
    const float* b_fc2    = (const float*)d_in[base + 10];
    const float* W_init   = (const float*)d_in[base + 11];
    const float* b_init   = (const float*)d_in[base + 12];
    float* out = (float*)d_out;

    float *sbias, *gates, *xs, *wpad, *h0, *c0, *h1, *c1, *hid, *pos;
    cudaGetSymbolAddress((void**)&sbias, g_sbias);
    cudaGetSymbolAddress((void**)&gates, g_gates);
    cudaGetSymbolAddress((void**)&xs,    g_xs);
    cudaGetSymbolAddress((void**)&wpad,  g_wpad);
    cudaGetSymbolAddress((void**)&h0,    g_h0);
    cudaGetSymbolAddress((void**)&c0,    g_c0);
    cudaGetSymbolAddress((void**)&h1,    g_h1);
    cudaGetSymbolAddress((void**)&c1,    g_c1);
    cudaGetSymbolAddress((void**)&hid,   g_hid);
    cudaGetSymbolAddress((void**)&pos,   g_pos);

    // ---- precompute ----
    build_xs<<<(NROWS * KPAD + 255) / 256, 256>>>(context, ball, roles, role_tab, xs);
    pad_w<<<(G4 * KPAD + 255) / 256, 256>>>(W_ih0, wpad);

    dim3 gridG(NROWS / 64, G4 / 64);   // 352 x 32
    // sbias = xs @ wpad^T + b0
    gemm_fused<false, false, true, false, false><<<gridG, 256>>>(
        sbias, G4,
        xs, KPAD, wpad, KPAD, KPAD,
        nullptr, 0, nullptr, 0, 0,
        b0, nullptr, 0, nullptr, nullptr, 0);

    init_state<<<(NROWS * HD + 255) / 256, 256>>>(init_pos0, W_init, b_init, h0, c0, h1, c1);
    init_pos<<<(NROWS * 2 + 255) / 256, 256>>>(init_pos0, pos);

    dim3 gridM(NROWS / 64, 256 / 64);  // 352 x 4 for fc1
    const int cellBlocks = (NROWS * (HD / 4) + 255) / 256;
    const int outBlocks  = (NROWS * 32 + 255) / 256;

    // ---- time loop ----
    for (int t = 0; t < TSTEPS; ++t) {
        // layer 0: gates = sbias + pos-rank2 + h0 @ W_hh0^T
        gemm_fused<false, true, false, true, false><<<gridG, 256>>>(
            gates, G4,
            h0, HD, W_hh0, HD, HD,
            nullptr, 0, nullptr, 0, 0,
            nullptr, sbias, G4, pos, W_ih0, INW);
        lstm_cell<<<cellBlocks, 256>>>(gates, h0, c0);

        // layer 1: gates = b1 + h0 @ W_ih1^T + h1 @ W_hh1^T
        gemm_fused<true, false, true, false, false><<<gridG, 256>>>(
            gates, G4,
            h0, HD, W_ih1, HD, HD,
            h1, HD, W_hh1, HD, HD,
            b1, nullptr, 0, nullptr, nullptr, 0);
        lstm_cell<<<cellBlocks, 256>>>(gates, h1, c1);

        // MLP: hid = relu(h1 @ W_fc1^T + b_fc1)
        gemm_fused<false, false, true, false, true><<<gridM, 256>>>(
            hid, 256,
            h1, HD, W_fc1, HD, HD,
            nullptr, 0, nullptr, 0, 0,
            b_fc1, nullptr, 0, nullptr, nullptr, 0);
        // out = hid @ W_fc2^T + b_fc2 ; write preds[t]; update pos
        mlp_out<<<outBlocks, 256>>>(hid, W_fc2, b_fc2, pos, out, t);
    }
}